// round 17
// baseline (speedup 1.0000x reference)
#include <cuda_runtime.h>

#define BB 256
#define TT 1024
#define DD 128
#define LL 16
#define OO 256

// ---- recurrence geometry (R14 — frozen, 912.8 us measured loop) ----
#define NTHR 256
#define RSM_TSTRIDE 272     // 32 u64 data + 2 u64 pad per thread

#define PART_OFF 0          // partial[4 chunk][2 batch][256 o] f32 = 8 KB
#define S_OFF    8192       // state [2 parity][2 batch][256] f32  = 4 KB
#define RSM_OFF  12288      // Rsm: 256 * 272 = 69632 -> end 81920
// ---- fused-agg prologue staging (reused nowhere else) ----
#define XS_OFF   81920      // xs [64][128] f32 = 32768 -> 114688
#define WS_OFF   114688     // ws [16][132] f32 = 8448  -> 123136
#define AS_OFF   123136     // as_[16][66]  f32 = 4224  -> 127360
#define SMEM_BYTES 127360

// +OO pad: loop prefetches agg[t+1] unconditionally at t = TT-1.
__device__ float g_agg[(size_t)BB * TT * OO + OO];

#define FMA2(acc, a, b) asm("fma.rn.f32x2 %0, %1, %2, %0;" : "+l"(acc) : "l"(a), "l"(b))
#define ADD2(d, a, b)   asm("add.rn.f32x2 %0, %1, %2;" : "=l"(d) : "l"(a), "l"(b))

__device__ __forceinline__ void lds_v2u64(unsigned long long& a, unsigned long long& b,
                                          unsigned int addr) {
    asm volatile("ld.shared.v2.u64 {%0, %1}, [%2];" : "=l"(a), "=l"(b) : "r"(addr));
}
__device__ __forceinline__ unsigned long long lds_u64(unsigned int addr) {
    unsigned long long v;
    asm volatile("ld.shared.u64 %0, [%1];" : "=l"(v) : "r"(addr)); return v;
}
__device__ __forceinline__ void sts_f32(unsigned int addr, float v) {
    asm volatile("st.shared.f32 [%0], %1;" :: "r"(addr), "f"(v));
}
__device__ __forceinline__ void sts_u64(unsigned int addr, unsigned long long v) {
    asm volatile("st.shared.u64 [%0], %1;" :: "r"(addr), "l"(v));
}
// plain (coherent) 64-bit global load — g_agg is written by THIS kernel
__device__ __forceinline__ unsigned long long ldg_u64(const float* p) {
    unsigned long long v;
    asm volatile("ld.global.b64 %0, [%1];" : "=l"(v) : "l"(p)); return v;
}
__device__ __forceinline__ void stg_u64(float* p, unsigned long long v) {
    asm volatile("st.global.b64 [%0], %1;" :: "l"(p), "l"(v) : "memory");
}

// ---------------------------------------------------------------------------
// Single fused kernel:
//   PROLOGUE: this CTA computes agg for its own 2 batches (rows
//             [b0*TT, (b0+2)*TT)) into g_agg — private, no cross-CTA deps.
//             Pre-stage = R11 math; matmul = R15 r-packed (both proven).
//   LOOP:     R14 recurrence VERBATIM (only .nc load dropped).
// ---------------------------------------------------------------------------
__global__ void __launch_bounds__(NTHR, 1) recur_kernel(
    const float* __restrict__ x, const float* __restrict__ subW,
    const float* __restrict__ subb, const float* __restrict__ aggW,
    const float* __restrict__ R, float* __restrict__ out)
{
    extern __shared__ unsigned char dyn[];
    unsigned int sm;
    asm("{ .reg .u64 t0; cvta.to.shared.u64 t0, %1; cvt.u32.u64 %0, t0; }"
        : "=r"(sm) : "l"(dyn));

    const int tid  = threadIdx.x;
    const int lane = tid & 31;
    const int w    = tid >> 5;
    const int c    = w & 3;        // k-chunk: rows 64c .. 64c+63
    const int h    = w >> 2;       // o-half
    const int b0   = blockIdx.x * 2;

    // =======================================================================
    // PROLOGUE: fused agg for this CTA's 2048 rows (32 blocks of 64)
    // =======================================================================
    {
        float (*xs)[DD]      = (float (*)[DD])(dyn + XS_OFF);
        float (*ws)[DD + 4]  = (float (*)[DD + 4])(dyn + WS_OFF);
        float (*as_)[66]     = (float (*)[66])(dyn + AS_OFF);

        // stage sub_W once
        for (int i = tid; i < LL * DD; i += 256) ws[i / DD][i % DD] = subW[i];

        // pre-stage identity
        const int pl  = tid & 15;
        const int prb = tid >> 4;
        const float bias = subb[pl];

        // matmul identity (R15 r-pack): thread = (o-pair op, r-half rh)
        const int op = tid & 127;
        const int rh = tid >> 7;
        const int o0 = op * 2;
        unsigned long long wd[LL][2];
#pragma unroll
        for (int l = 0; l < LL; l++) {
            const float w0 = aggW[l * OO + o0];
            const float w1 = aggW[l * OO + o0 + 1];
            asm("mov.b64 %0, {%1, %1};" : "=l"(wd[l][0]) : "f"(w0));
            asm("mov.b64 %0, {%1, %1};" : "=l"(wd[l][1]) : "f"(w1));
        }

        const size_t rowbase = (size_t)b0 * TT;
        __syncthreads();

        for (int blk = 0; blk < 32; blk++) {
            const size_t row0 = rowbase + (size_t)blk * 64;

            // ---- stage 64 x-rows (float4, coalesced)
            {
                const float4* xg = (const float4*)(x + row0 * DD);
                float4* xs4 = (float4*)&xs[0][0];
#pragma unroll
                for (int i = 0; i < 8; i++) xs4[tid + 256 * i] = xg[tid + 256 * i];
            }
            __syncthreads();

            // ---- pre + activation: 4 rows per thread, f32x2 dot over D=128
            {
                const ulonglong2* wr = (const ulonglong2*)&ws[pl][0];
#pragma unroll
                for (int it = 0; it < 4; it++) {
                    const int r = prb + 16 * it;
                    const ulonglong2* xr = (const ulonglong2*)&xs[r][0];
                    unsigned long long acc = 0ULL;
#pragma unroll
                    for (int i = 0; i < 32; i++) {
                        ulonglong2 a = xr[i], b = wr[i];
                        FMA2(acc, a.x, b.x);
                        FMA2(acc, a.y, b.y);
                    }
                    float lo, hi;
                    asm("mov.b64 {%0, %1}, %2;" : "=f"(lo), "=f"(hi) : "l"(acc));
                    const float s = lo + hi + bias;
                    float v;
                    const int m = pl & 3;
                    if (m == 0)      v = tanhf(s);
                    else if (m == 1) v = fmaxf(s, 0.f);
                    else if (m == 2) v = 1.f / (1.f + expf(-s));
                    else             v = s;
                    as_[pl][r] = v;                 // transposed store (conflict-free)
                }
            }
            __syncthreads();

            // ---- matmul, r-packed: acc f32x2 = (out[r0][o], out[r0+1][o])
            {
                float* outp = g_agg + (row0 + rh * 32) * (size_t)OO + o0;
#pragma unroll
                for (int rp = 0; rp < 16; rp++) {
                    const int r0 = rh * 32 + 2 * rp;
                    unsigned long long acc0 = 0, acc1 = 0;
#pragma unroll
                    for (int l = 0; l < LL; l++) {
                        const unsigned long long av =
                            *(const unsigned long long*)&as_[l][r0];  // broadcast LDS.64
                        FMA2(acc0, av, wd[l][0]);
                        FMA2(acc1, av, wd[l][1]);
                    }
                    float a0lo, a0hi, a1lo, a1hi;
                    asm("mov.b64 {%0, %1}, %2;" : "=f"(a0lo), "=f"(a0hi) : "l"(acc0));
                    asm("mov.b64 {%0, %1}, %2;" : "=f"(a1lo), "=f"(a1hi) : "l"(acc1));
                    float2 v0; v0.x = a0lo; v0.y = a1lo;
                    float2 v1; v1.x = a0hi; v1.y = a1hi;
                    *(float2*)(outp + (size_t)(2 * rp)     * OO) = v0;
                    *(float2*)(outp + (size_t)(2 * rp + 1) * OO) = v1;
                }
            }
            __syncthreads();
        }
    }
    // g_agg rows for this CTA are complete and visible (last __syncthreads).

    // =======================================================================
    // LOOP: R14 recurrence — VERBATIM except plain (non-.nc) agg loads
    // =======================================================================

    // ---- 24 k-pairs (48 rows) x 4 o-cols into registers
    unsigned long long Rp[24 * 4];
#pragma unroll
    for (int i = 0; i < 24; i++)
#pragma unroll
        for (int j = 0; j < 4; j++) {
            const int k = c * 64 + 2 * i;
            const int o = h * 128 + lane + 32 * j;
            float lo = R[(size_t)k * OO + o];
            float hi = R[(size_t)(k + 1) * OO + o];
            asm("mov.b64 %0, {%1, %2};" : "=l"(Rp[i * 4 + j]) : "f"(lo), "f"(hi));
        }

    // ---- 8 k-pairs (16 rows) x 4 o-cols into per-thread smem rows
    const unsigned int rsm = sm + RSM_OFF + tid * RSM_TSTRIDE;
#pragma unroll
    for (int i = 0; i < 8; i++)
#pragma unroll
        for (int j = 0; j < 4; j++) {
            const int k = c * 64 + 48 + 2 * i;
            const int o = h * 128 + lane + 32 * j;
            float lo = R[(size_t)k * OO + o];
            float hi = R[(size_t)(k + 1) * OO + o];
            unsigned long long p;
            asm("mov.b64 %0, {%1, %2};" : "=l"(p) : "f"(lo), "f"(hi));
            sts_u64(rsm + (unsigned)(i * 4 + j) * 8, p);
        }

    // ---- phase-2 identity: thread = (o-pair op2, batch bt)
    const int op2 = tid & 127;     // o columns 2*op2, 2*op2+1
    const int bt  = tid >> 7;

    // zero initial state, parity-0 buffer
    sts_u64(sm + S_OFF + bt * 1024 + op2 * 8, 0ULL);

    const float* aggp  = g_agg + ((size_t)(b0 + bt) * TT) * OO + 2 * op2;
    const float* aggpn = aggp + OO;                    // prefetch cursor (t+1)
    float*       outp  = out   + ((size_t)(b0 + bt) * TT) * OO + 2 * op2;
    unsigned long long a_cur = ldg_u64(aggp);          // (agg[o0], agg[o1]) at t=0

    // addresses
    const unsigned int schunk = sm + S_OFF + c * 256;
    const unsigned int pw     = sm + PART_OFF + c * 2048 + (h * 128 + lane) * 4;
    const unsigned int prb2   = sm + PART_OFF + bt * 1024 + op2 * 8;
    const unsigned int swb    = sm + S_OFF + bt * 1024 + op2 * 8;

    __syncthreads();

#define RSTEP(SR, SW)                                                           \
    {                                                                           \
        const unsigned long long a_nxt = ldg_u64(aggpn); aggpn += OO;           \
        const unsigned int sA = schunk + (SR);                                  \
        const unsigned int sB = sA + 1024;                                      \
        unsigned long long acc0 = 0, acc1 = 0, acc2 = 0, acc3 = 0,              \
                           acc4 = 0, acc5 = 0, acc6 = 0, acc7 = 0;              \
        _Pragma("unroll")                                                       \
        for (int ii = 0; ii < 12; ii++) {                                       \
            unsigned long long ax, ay, bx, by;                                  \
            lds_v2u64(ax, ay, sA + ii * 16);                                    \
            lds_v2u64(bx, by, sB + ii * 16);                                    \
            FMA2(acc0, ax, Rp[(2*ii)*4+0]);   FMA2(acc4, bx, Rp[(2*ii)*4+0]);   \
            FMA2(acc1, ax, Rp[(2*ii)*4+1]);   FMA2(acc5, bx, Rp[(2*ii)*4+1]);   \
            FMA2(acc2, ax, Rp[(2*ii)*4+2]);   FMA2(acc6, bx, Rp[(2*ii)*4+2]);   \
            FMA2(acc3, ax, Rp[(2*ii)*4+3]);   FMA2(acc7, bx, Rp[(2*ii)*4+3]);   \
            FMA2(acc0, ay, Rp[(2*ii+1)*4+0]); FMA2(acc4, by, Rp[(2*ii+1)*4+0]); \
            FMA2(acc1, ay, Rp[(2*ii+1)*4+1]); FMA2(acc5, by, Rp[(2*ii+1)*4+1]); \
            FMA2(acc2, ay, Rp[(2*ii+1)*4+2]); FMA2(acc6, by, Rp[(2*ii+1)*4+2]); \
            FMA2(acc3, ay, Rp[(2*ii+1)*4+3]); FMA2(acc7, by, Rp[(2*ii+1)*4+3]); \
        }                                                                       \
        _Pragma("unroll")                                                       \
        for (int q = 0; q < 4; q++) {                                           \
            unsigned long long ax, ay, bx, by, r0, r1, r2, r3;                  \
            lds_v2u64(ax, ay, sA + (12 + q) * 16);                              \
            lds_v2u64(bx, by, sB + (12 + q) * 16);                              \
            lds_v2u64(r0, r1, rsm + (2*q) * 32);                                \
            lds_v2u64(r2, r3, rsm + (2*q) * 32 + 16);                           \
            FMA2(acc0, ax, r0); FMA2(acc4, bx, r0);                             \
            FMA2(acc1, ax, r1); FMA2(acc5, bx, r1);                             \
            FMA2(acc2, ax, r2); FMA2(acc6, bx, r2);                             \
            FMA2(acc3, ax, r3); FMA2(acc7, bx, r3);                             \
            lds_v2u64(r0, r1, rsm + (2*q+1) * 32);                              \
            lds_v2u64(r2, r3, rsm + (2*q+1) * 32 + 16);                         \
            FMA2(acc0, ay, r0); FMA2(acc4, by, r0);                             \
            FMA2(acc1, ay, r1); FMA2(acc5, by, r1);                             \
            FMA2(acc2, ay, r2); FMA2(acc6, by, r2);                             \
            FMA2(acc3, ay, r3); FMA2(acc7, by, r3);                             \
        }                                                                       \
        {                                                                       \
            float fx, fy;                                                       \
            asm("mov.b64 {%0,%1}, %2;" : "=f"(fx), "=f"(fy) : "l"(acc0));       \
            sts_f32(pw + 0*1024 + 0*128, fx + fy);                              \
            asm("mov.b64 {%0,%1}, %2;" : "=f"(fx), "=f"(fy) : "l"(acc1));       \
            sts_f32(pw + 0*1024 + 1*128, fx + fy);                              \
            asm("mov.b64 {%0,%1}, %2;" : "=f"(fx), "=f"(fy) : "l"(acc2));       \
            sts_f32(pw + 0*1024 + 2*128, fx + fy);                              \
            asm("mov.b64 {%0,%1}, %2;" : "=f"(fx), "=f"(fy) : "l"(acc3));       \
            sts_f32(pw + 0*1024 + 3*128, fx + fy);                              \
            asm("mov.b64 {%0,%1}, %2;" : "=f"(fx), "=f"(fy) : "l"(acc4));       \
            sts_f32(pw + 1*1024 + 0*128, fx + fy);                              \
            asm("mov.b64 {%0,%1}, %2;" : "=f"(fx), "=f"(fy) : "l"(acc5));       \
            sts_f32(pw + 1*1024 + 1*128, fx + fy);                              \
            asm("mov.b64 {%0,%1}, %2;" : "=f"(fx), "=f"(fy) : "l"(acc6));       \
            sts_f32(pw + 1*1024 + 2*128, fx + fy);                              \
            asm("mov.b64 {%0,%1}, %2;" : "=f"(fx), "=f"(fy) : "l"(acc7));       \
            sts_f32(pw + 1*1024 + 3*128, fx + fy);                              \
        }                                                                       \
        __syncthreads();                                                        \
        {                                                                       \
            unsigned long long r = a_cur;                                       \
            ADD2(r, r, lds_u64(prb2 + 0*2048));                                 \
            ADD2(r, r, lds_u64(prb2 + 1*2048));                                 \
            ADD2(r, r, lds_u64(prb2 + 2*2048));                                 \
            ADD2(r, r, lds_u64(prb2 + 3*2048));                                 \
            sts_u64(swb + (SW), r);                                             \
            stg_u64(outp, r); outp += OO;                                       \
        }                                                                       \
        a_cur = a_nxt;                                                          \
        __syncthreads();                                                        \
    }

    for (int t = 0; t < TT; t += 2) {
        RSTEP(0, 2048);      // even step: read parity 0, write parity 1
        RSTEP(2048, 0);      // odd step:  read parity 1, write parity 0
    }
#undef RSTEP
}

// ---------------------------------------------------------------------------
extern "C" void kernel_launch(void* const* d_in, const int* in_sizes, int n_in,
                              void* d_out, int out_size)
{
    const float* x    = (const float*)d_in[0];
    const float* subW = (const float*)d_in[1];
    const float* subb = (const float*)d_in[2];
    const float* aggW = (const float*)d_in[3];
    const float* R    = (const float*)d_in[4];
    float* out = (float*)d_out;

    cudaFuncSetAttribute(recur_kernel, cudaFuncAttributeMaxDynamicSharedMemorySize,
                         SMEM_BYTES);

    recur_kernel<<<BB / 2, NTHR, SMEM_BYTES>>>(x, subW, subb, aggW, R, out);
}